// round 1
// baseline (speedup 1.0000x reference)
#include <cuda_runtime.h>
#include <math.h>
#include <float.h>

// Shapes (fixed by the problem)
#define Nn 16
#define Cc 64
#define Ff 8
#define HWs 3136              // 56*56
#define ROWS (Nn*Cc*Ff)       // 8192
#define CNT0 401408.0f        // Nn*Ff*HWs
#define EPS 1e-5f

// ---- scratch (device globals; no allocation allowed) ----
__device__ float g_sum0[Cc], g_ss0[Cc];
__device__ float g_top5[ROWS * 5];
__device__ float g_si[Nn * Cc * 7 * 20];     // 143360
__device__ float g_x1[Nn * 128 * 7 * 10];    // 143360
__device__ float g_s1[128], g_q1[128];
__device__ float g_x2[Nn * 256 * 7 * 5];     // 143360
__device__ float g_s2[256], g_q2[256];

// ---------------------------------------------------------------------------
__global__ void k_init() {
    int t = threadIdx.x;
    if (t < Cc)  { g_sum0[t] = 0.f; g_ss0[t] = 0.f; }
    if (t < 128) { g_s1[t] = 0.f;   g_q1[t] = 0.f; }
    g_s2[t] = 0.f; g_q2[t] = 0.f;   // blockDim = 256
}

// ---------------------------------------------------------------------------
// One block per (n,c,f) row of 3136 floats: single pass -> row top-5 (raw)
// + per-channel sum/sumsq (BatchNorm3d batch stats).
// Valid because BN is a monotone-increasing per-channel affine (g > 0), so
// top5(bn(x)) == bn(top5(x)).
__global__ void k_topk(const float* __restrict__ h) {
    int row = blockIdx.x;            // ((n*Cc + c)*Ff + f)
    int c   = (row / Ff) % Cc;
    const float4* p4 = reinterpret_cast<const float4*>(h + (size_t)row * HWs);
    int tid = threadIdx.x;

    float a0 = -FLT_MAX, a1 = -FLT_MAX, a2 = -FLT_MAX, a3 = -FLT_MAX, a4 = -FLT_MAX;
    float s = 0.f, ss = 0.f;

#define INS(vv) { float _v = (vv); s += _v; ss += _v * _v;          \
    if (_v > a4) {                                                   \
        if      (_v > a0) { a4=a3; a3=a2; a2=a1; a1=a0; a0=_v; }     \
        else if (_v > a1) { a4=a3; a3=a2; a2=a1; a1=_v; }            \
        else if (_v > a2) { a4=a3; a3=a2; a2=_v; }                   \
        else if (_v > a3) { a4=a3; a3=_v; }                          \
        else              { a4=_v; } } }

    for (int i = tid; i < 784; i += 256) {   // 3136/4 float4s, coalesced
        float4 v = p4[i];
        INS(v.x); INS(v.y); INS(v.z); INS(v.w);
    }
#undef INS

    // sum/sumsq reduce: warp shuffle + 8 partials
    float wsum = s, wss = ss;
    #pragma unroll
    for (int o = 16; o; o >>= 1) {
        wsum += __shfl_xor_sync(0xffffffffu, wsum, o);
        wss  += __shfl_xor_sync(0xffffffffu, wss,  o);
    }
    __shared__ float r1[8], r2[8];
    int lane = tid & 31, wid = tid >> 5;
    if (lane == 0) { r1[wid] = wsum; r2[wid] = wss; }

    // top-5 merge tree in shared (sorted-descending 5-lists)
    __shared__ float s5[256 * 5];
    s5[tid*5+0]=a0; s5[tid*5+1]=a1; s5[tid*5+2]=a2; s5[tid*5+3]=a3; s5[tid*5+4]=a4;
    __syncthreads();
    for (int stride = 128; stride >= 1; stride >>= 1) {
        if (tid < stride) {
            float* A = &s5[tid * 5];
            float* B = &s5[(tid + stride) * 5];
            float out[5];
            int i = 0, j = 0;
            #pragma unroll
            for (int k = 0; k < 5; k++) {
                float av = A[i], bv = B[j];
                if (av >= bv) { out[k] = av; i++; } else { out[k] = bv; j++; }
            }
            #pragma unroll
            for (int k = 0; k < 5; k++) A[k] = out[k];
        }
        __syncthreads();
    }

    if (tid == 0) {
        float S = 0.f, SS = 0.f;
        #pragma unroll
        for (int i = 0; i < 8; i++) { S += r1[i]; SS += r2[i]; }
        atomicAdd(&g_sum0[c], S);
        atomicAdd(&g_ss0[c], SS);
        #pragma unroll
        for (int k = 0; k < 5; k++) g_top5[row * 5 + k] = s5[k];
    }
}

// ---------------------------------------------------------------------------
// One block per (n,c): 8 warps handle the 8 F-rows (5->25->tanh->softmax->cen),
// then the temporal (7x20) attention, writes si (N,C,7,20).
__global__ void k_attn(const float* __restrict__ bn0_g, const float* __restrict__ bn0_b,
                       const float* __restrict__ up_w,  const float* __restrict__ up_b,
                       const float* __restrict__ up2_w, const float* __restrict__ up2_b,
                       const float* __restrict__ up3_w, const float* __restrict__ up3_b,
                       const float* __restrict__ wW,    const float* __restrict__ wproj,
                       const float* __restrict__ wW2,   const float* __restrict__ wproj2) {
    __shared__ float s_up2w[125], s_up2b[25], s_wW[625], s_wproj[125], s_up3w[125], s_up3b[5];
    __shared__ float s_upw[40], s_upb[20], s_wW2[49], s_wproj2[20];
    __shared__ float sh_t[8][25], sh_u[8][25], sh_l[8][5], sh_m[8][5], sh_cen[8][2];
    __shared__ float sh_d[7][20], sh_u2[7][20], sh_l2[7], sh_a2[7];

    int tid = threadIdx.x;
    for (int i = tid; i < 125; i += 256) s_up2w[i] = up2_w[i];
    for (int i = tid; i < 625; i += 256) s_wW[i]   = wW[i];
    for (int i = tid; i < 125; i += 256) s_wproj[i]= wproj[i];
    for (int i = tid; i < 125; i += 256) s_up3w[i] = up3_w[i];
    if (tid < 25) s_up2b[tid] = up2_b[tid];
    if (tid < 5)  s_up3b[tid] = up3_b[tid];
    if (tid < 40) s_upw[tid]  = up_w[tid];
    if (tid < 20) s_upb[tid]  = up_b[tid];
    if (tid < 49) s_wW2[tid]  = wW2[tid];
    if (tid < 20) s_wproj2[tid] = wproj2[tid];

    int nc = blockIdx.x;
    int c  = nc % Cc;
    float mean = g_sum0[c] / CNT0;
    float var  = g_ss0[c] / CNT0 - mean * mean;
    float bsc  = rsqrtf(var + EPS) * bn0_g[c];
    float bsh  = bn0_b[c] - mean * bsc;
    __syncthreads();

    int wf = tid >> 5, lane = tid & 31;
    float tv[5];
    {
        int row = nc * 8 + wf;
        #pragma unroll
        for (int k = 0; k < 5; k++) tv[k] = g_top5[row * 5 + k] * bsc + bsh;
    }
    if (lane < 25) {
        float a = s_up2b[lane];
        #pragma unroll
        for (int k = 0; k < 5; k++) a += tv[k] * s_up2w[lane * 5 + k];
        sh_t[wf][lane] = a;
    }
    __syncwarp();
    if (lane < 25) {
        float a = 0.f;
        #pragma unroll
        for (int i = 0; i < 25; i++) a += sh_t[wf][i] * s_wW[i * 25 + lane];
        sh_u[wf][lane] = tanhf(a);
    }
    __syncwarp();
    if (lane < 5) {
        float a = 0.f;
        #pragma unroll
        for (int i = 0; i < 25; i++) a += sh_u[wf][i] * s_wproj[i * 5 + lane];
        sh_l[wf][lane] = a;
    }
    __syncwarp();
    if (lane < 5) {
        float mx = sh_l[wf][0];
        #pragma unroll
        for (int j = 1; j < 5; j++) mx = fmaxf(mx, sh_l[wf][j]);
        float den = 0.f;
        #pragma unroll
        for (int j = 0; j < 5; j++) den += expf(sh_l[wf][j] - mx);
        float att = expf(sh_l[wf][lane] - mx) / den;
        float t3  = s_up3b[lane];
        #pragma unroll
        for (int i = 0; i < 25; i++) t3 += sh_t[wf][i] * s_up3w[lane * 25 + i];
        sh_m[wf][lane] = t3 * att;
    }
    __syncwarp();
    float c0 = 0.f, c1 = 0.f;
    if (lane < 25) {
        float sc = s_up2b[lane];
        #pragma unroll
        for (int k = 0; k < 5; k++) sc += sh_m[wf][k] * s_up2w[lane * 5 + k];
        c0 = sc * (float)(lane / 5);   // coords col 0 (ii)
        c1 = sc * (float)(lane % 5);   // coords col 1 (jj)
    }
    #pragma unroll
    for (int o = 16; o; o >>= 1) {
        c0 += __shfl_xor_sync(0xffffffffu, c0, o);
        c1 += __shfl_xor_sync(0xffffffffu, c1, o);
    }
    if (lane == 0) { sh_cen[wf][0] = c0; sh_cen[wf][1] = c1; }
    __syncthreads();

    // temporal attention (7 diffs, 20-dim embed)
    if (tid < 140) {
        int j = tid / 20, k = tid % 20;
        float d0 = sh_cen[j + 1][0] - sh_cen[j][0];
        float d1 = sh_cen[j + 1][1] - sh_cen[j][1];
        sh_d[j][k] = d0 * s_upw[k * 2] + d1 * s_upw[k * 2 + 1] + s_upb[k];
    }
    __syncthreads();
    if (tid < 140) {
        int i = tid / 20, k = tid % 20;
        float a = 0.f;
        #pragma unroll
        for (int j = 0; j < 7; j++) a += s_wW2[i * 7 + j] * sh_d[j][k];
        sh_u2[i][k] = tanhf(a);
    }
    __syncthreads();
    if (tid < 7) {
        float a = 0.f;
        #pragma unroll
        for (int k = 0; k < 20; k++) a += sh_u2[tid][k] * s_wproj2[k];
        sh_l2[tid] = a;
    }
    __syncthreads();
    if (tid < 7) {
        float mx = sh_l2[0];
        #pragma unroll
        for (int i = 1; i < 7; i++) mx = fmaxf(mx, sh_l2[i]);
        float den = 0.f;
        #pragma unroll
        for (int i = 0; i < 7; i++) den += expf(sh_l2[i] - mx);
        sh_a2[tid] = expf(sh_l2[tid] - mx) / den;
    }
    __syncthreads();
    if (tid < 140) {
        int i = tid / 20, k = tid % 20;
        g_si[(nc * 7 + i) * 20 + k] = sh_d[i][k] * sh_a2[i];
    }
}

// ---------------------------------------------------------------------------
// conv1: (N,64,7,20) -> (N,128,7,10), kernel (1,3), stride (1,2), pad W=1.
// Block = (n,i); thread = out channel o. Also accumulates bn1 batch stats.
__global__ void k_conv1(const float* __restrict__ w) {
    int b = blockIdx.x; int n = b / 7, i = b % 7;
    __shared__ float s_in[64 * 20];
    int tid = threadIdx.x;   // 128
    for (int idx = tid; idx < 1280; idx += 128) {
        int cc = idx / 20, k = idx % 20;
        s_in[idx] = g_si[((n * 64 + cc) * 7 + i) * 20 + k];
    }
    __syncthreads();
    int o = tid;
    float x[10];
    #pragma unroll
    for (int j = 0; j < 10; j++) x[j] = 0.f;
    const float* wo = w + o * 64 * 3;
    for (int cc = 0; cc < 64; cc++) {
        float w0 = wo[cc*3], w1 = wo[cc*3+1], w2 = wo[cc*3+2];
        const float* s = &s_in[cc * 20];
        x[0] += s[0] * w1 + s[1] * w2;                 // pad-left skip
        #pragma unroll
        for (int j = 1; j < 10; j++)
            x[j] += s[2*j-1] * w0 + s[2*j] * w1 + s[2*j+1] * w2;
    }
    float ps = 0.f, pq = 0.f;
    #pragma unroll
    for (int j = 0; j < 10; j++) {
        g_x1[((n * 128 + o) * 7 + i) * 10 + j] = x[j];
        ps += x[j]; pq += x[j] * x[j];
    }
    atomicAdd(&g_s1[o], ps);
    atomicAdd(&g_q1[o], pq);
}

// ---------------------------------------------------------------------------
// bn1 + tanh + conv2: (N,128,7,10) -> (N,256,7,5). Accumulates bn2 stats.
__global__ void k_conv2(const float* __restrict__ w,
                        const float* __restrict__ g1, const float* __restrict__ b1) {
    int b = blockIdx.x; int n = b / 7, i = b % 7;
    __shared__ float s_a[128 * 10];
    __shared__ float s_sc[128], s_sh[128];
    int tid = threadIdx.x;   // 256
    if (tid < 128) {
        float mean = g_s1[tid] / 1120.f;
        float var  = g_q1[tid] / 1120.f - mean * mean;
        float sc   = rsqrtf(var + EPS) * g1[tid];
        s_sc[tid] = sc; s_sh[tid] = b1[tid] - mean * sc;
    }
    __syncthreads();
    for (int idx = tid; idx < 1280; idx += 256) {
        int cc = idx / 10, k = idx % 10;
        float v = g_x1[((n * 128 + cc) * 7 + i) * 10 + k];
        s_a[idx] = tanhf(v * s_sc[cc] + s_sh[cc]);
    }
    __syncthreads();
    int o = tid;
    float y[5] = {0.f, 0.f, 0.f, 0.f, 0.f};
    const float* wo = w + o * 128 * 3;
    for (int cc = 0; cc < 128; cc++) {
        float w0 = wo[cc*3], w1 = wo[cc*3+1], w2 = wo[cc*3+2];
        const float* s = &s_a[cc * 10];
        y[0] += s[0] * w1 + s[1] * w2;
        #pragma unroll
        for (int j = 1; j < 5; j++)
            y[j] += s[2*j-1] * w0 + s[2*j] * w1 + s[2*j+1] * w2;
    }
    float ps = 0.f, pq = 0.f;
    #pragma unroll
    for (int j = 0; j < 5; j++) {
        g_x2[((n * 256 + o) * 7 + i) * 5 + j] = y[j];
        ps += y[j]; pq += y[j] * y[j];
    }
    atomicAdd(&g_s2[o], ps);
    atomicAdd(&g_q2[o], pq);
}

// ---------------------------------------------------------------------------
// bn2 + tanh + mean over W(5) -> out (N,256,7,1)
__global__ void k_final(const float* __restrict__ g2, const float* __restrict__ b2,
                        float* __restrict__ out) {
    int b = blockIdx.x; int n = b / 7, i = b % 7;
    int o = threadIdx.x;   // 256
    float mean = g_s2[o] / 560.f;
    float var  = g_q2[o] / 560.f - mean * mean;
    float sc   = rsqrtf(var + EPS) * g2[o];
    float sh   = b2[o] - mean * sc;
    float acc = 0.f;
    #pragma unroll
    for (int j = 0; j < 5; j++)
        acc += tanhf(g_x2[((n * 256 + o) * 7 + i) * 5 + j] * sc + sh);
    out[(n * 256 + o) * 7 + i] = acc * 0.2f;
}

// ---------------------------------------------------------------------------
extern "C" void kernel_launch(void* const* d_in, const int* in_sizes, int n_in,
                              void* d_out, int out_size) {
    const float* h       = (const float*)d_in[0];
    const float* bn0_g   = (const float*)d_in[1];
    const float* bn0_b   = (const float*)d_in[2];
    const float* up_w    = (const float*)d_in[3];
    const float* up_b    = (const float*)d_in[4];
    const float* up2_w   = (const float*)d_in[5];
    const float* up2_b   = (const float*)d_in[6];
    const float* up3_w   = (const float*)d_in[7];
    const float* up3_b   = (const float*)d_in[8];
    const float* wW      = (const float*)d_in[9];
    const float* wproj   = (const float*)d_in[10];
    const float* wW2     = (const float*)d_in[11];
    const float* wproj2  = (const float*)d_in[12];
    const float* conv1_w = (const float*)d_in[13];
    const float* bn1_g   = (const float*)d_in[14];
    const float* bn1_b   = (const float*)d_in[15];
    const float* conv2_w = (const float*)d_in[16];
    const float* bn2_g   = (const float*)d_in[17];
    const float* bn2_b   = (const float*)d_in[18];

    k_init <<<1, 256>>>();
    k_topk <<<ROWS, 256>>>(h);
    k_attn <<<Nn * Cc, 256>>>(bn0_g, bn0_b, up_w, up_b, up2_w, up2_b,
                              up3_w, up3_b, wW, wproj, wW2, wproj2);
    k_conv1<<<Nn * 7, 128>>>(conv1_w);
    k_conv2<<<Nn * 7, 256>>>(conv2_w, bn1_g, bn1_b);
    k_final<<<Nn * 7, 256>>>(bn2_g, bn2_b, (float*)d_out);
}

// round 2
// speedup vs baseline: 1.1385x; 1.1385x over previous
#include <cuda_runtime.h>
#include <math.h>
#include <float.h>

// Shapes (fixed by the problem)
#define Nn 16
#define Cc 64
#define Ff 8
#define HWs 3136              // 56*56
#define ROWS (Nn*Cc*Ff)       // 8192
#define CNT0 401408.0f        // Nn*Ff*HWs
#define EPS 1e-5f

// ---- scratch (device globals; no allocation allowed) ----
__device__ float g_sum0[Cc], g_ss0[Cc];
__device__ float g_top5[ROWS * 5];
__device__ float g_si[Nn * Cc * 7 * 20];     // 143360
__device__ float g_x1[Nn * 128 * 7 * 10];    // 143360
__device__ float g_s1[128], g_q1[128];
__device__ float g_x2[Nn * 256 * 7 * 5];     // 143360
__device__ float g_s2[256], g_q2[256];
// packed conv weights: [cc][o][4] (tap 3 = 0) for vectorized float4 loads
__device__ float p1w[64 * 128 * 4];          // 128 KB
__device__ float p2w[128 * 256 * 4];         // 512 KB

// ---------------------------------------------------------------------------
// One launch: pack conv1/conv2 weights into [cc][o][4] + zero stat accumulators.
__global__ void k_prep(const float* __restrict__ w1, const float* __restrict__ w2) {
    int b = blockIdx.x, t = threadIdx.x;
    if (b < 128) {                       // p1: 32768 elements
        int idx = b * 256 + t;
        int cc = idx >> 9, rem = idx & 511, o = rem >> 2, tap = rem & 3;
        p1w[idx] = (tap < 3) ? w1[o * 192 + cc * 3 + tap] : 0.f;
    } else if (b < 640) {                // p2: 131072 elements
        int idx = (b - 128) * 256 + t;
        int cc = idx >> 10, rem = idx & 1023, o = rem >> 2, tap = rem & 3;
        p2w[idx] = (tap < 3) ? w2[o * 384 + cc * 3 + tap] : 0.f;
    } else {
        if (t < Cc)  { g_sum0[t] = 0.f; g_ss0[t] = 0.f; }
        if (t < 128) { g_s1[t] = 0.f;   g_q1[t] = 0.f; }
        g_s2[t] = 0.f; g_q2[t] = 0.f;
    }
}

// ---------------------------------------------------------------------------
// One block per (n,c,f) row of 3136 floats: single pass -> row top-5 (raw)
// + per-channel sum/sumsq (BatchNorm3d batch stats).
// Valid because BN is a monotone-increasing per-channel affine (g > 0), so
// top5(bn(x)) == bn(top5(x)).
__global__ void k_topk(const float* __restrict__ h) {
    int row = blockIdx.x;            // ((n*Cc + c)*Ff + f)
    int c   = (row / Ff) % Cc;
    const float4* p4 = reinterpret_cast<const float4*>(h + (size_t)row * HWs);
    int tid = threadIdx.x;

    float a0 = -FLT_MAX, a1 = -FLT_MAX, a2 = -FLT_MAX, a3 = -FLT_MAX, a4 = -FLT_MAX;
    float s = 0.f, ss = 0.f;

#define INS(vv) { float _v = (vv); s += _v; ss += _v * _v;          \
    if (_v > a4) {                                                   \
        if      (_v > a0) { a4=a3; a3=a2; a2=a1; a1=a0; a0=_v; }     \
        else if (_v > a1) { a4=a3; a3=a2; a2=a1; a1=_v; }            \
        else if (_v > a2) { a4=a3; a3=a2; a2=_v; }                   \
        else if (_v > a3) { a4=a3; a3=_v; }                          \
        else              { a4=_v; } } }

    for (int i = tid; i < 784; i += 256) {   // 3136/4 float4s, coalesced
        float4 v = p4[i];
        INS(v.x); INS(v.y); INS(v.z); INS(v.w);
    }
#undef INS

    // sum/sumsq reduce: warp shuffle + 8 partials
    float wsum = s, wss = ss;
    #pragma unroll
    for (int o = 16; o; o >>= 1) {
        wsum += __shfl_xor_sync(0xffffffffu, wsum, o);
        wss  += __shfl_xor_sync(0xffffffffu, wss,  o);
    }
    __shared__ float r1[8], r2[8];
    int lane = tid & 31, wid = tid >> 5;
    if (lane == 0) { r1[wid] = wsum; r2[wid] = wss; }

    // top-5 merge tree in shared (sorted-descending 5-lists)
    __shared__ float s5[256 * 5];
    s5[tid*5+0]=a0; s5[tid*5+1]=a1; s5[tid*5+2]=a2; s5[tid*5+3]=a3; s5[tid*5+4]=a4;
    __syncthreads();
    for (int stride = 128; stride >= 1; stride >>= 1) {
        if (tid < stride) {
            float* A = &s5[tid * 5];
            float* B = &s5[(tid + stride) * 5];
            float out[5];
            int i = 0, j = 0;
            #pragma unroll
            for (int k = 0; k < 5; k++) {
                float av = A[i], bv = B[j];
                if (av >= bv) { out[k] = av; i++; } else { out[k] = bv; j++; }
            }
            #pragma unroll
            for (int k = 0; k < 5; k++) A[k] = out[k];
        }
        __syncthreads();
    }

    if (tid == 0) {
        float S = 0.f, SS = 0.f;
        #pragma unroll
        for (int i = 0; i < 8; i++) { S += r1[i]; SS += r2[i]; }
        atomicAdd(&g_sum0[c], S);
        atomicAdd(&g_ss0[c], SS);
        #pragma unroll
        for (int k = 0; k < 5; k++) g_top5[row * 5 + k] = s5[k];
    }
}

// ---------------------------------------------------------------------------
// One block per (n,c): 8 warps handle the 8 F-rows (5->25->tanh->softmax->cen),
// then the temporal (7x20) attention, writes si (N,C,7,20).
__global__ void k_attn(const float* __restrict__ bn0_g, const float* __restrict__ bn0_b,
                       const float* __restrict__ up_w,  const float* __restrict__ up_b,
                       const float* __restrict__ up2_w, const float* __restrict__ up2_b,
                       const float* __restrict__ up3_w, const float* __restrict__ up3_b,
                       const float* __restrict__ wW,    const float* __restrict__ wproj,
                       const float* __restrict__ wW2,   const float* __restrict__ wproj2) {
    __shared__ float s_up2w[125], s_up2b[25], s_wW[625], s_wproj[125], s_up3w[125], s_up3b[5];
    __shared__ float s_upw[40], s_upb[20], s_wW2[49], s_wproj2[20];
    __shared__ float sh_t[8][25], sh_u[8][25], sh_l[8][5], sh_m[8][5], sh_cen[8][2];
    __shared__ float sh_d[7][20], sh_u2[7][20], sh_l2[7], sh_a2[7];

    int tid = threadIdx.x;
    for (int i = tid; i < 125; i += 256) s_up2w[i] = up2_w[i];
    for (int i = tid; i < 625; i += 256) s_wW[i]   = wW[i];
    for (int i = tid; i < 125; i += 256) s_wproj[i]= wproj[i];
    for (int i = tid; i < 125; i += 256) s_up3w[i] = up3_w[i];
    if (tid < 25) s_up2b[tid] = up2_b[tid];
    if (tid < 5)  s_up3b[tid] = up3_b[tid];
    if (tid < 40) s_upw[tid]  = up_w[tid];
    if (tid < 20) s_upb[tid]  = up_b[tid];
    if (tid < 49) s_wW2[tid]  = wW2[tid];
    if (tid < 20) s_wproj2[tid] = wproj2[tid];

    int nc = blockIdx.x;
    int c  = nc % Cc;
    float mean = g_sum0[c] / CNT0;
    float var  = g_ss0[c] / CNT0 - mean * mean;
    float bsc  = rsqrtf(var + EPS) * bn0_g[c];
    float bsh  = bn0_b[c] - mean * bsc;
    __syncthreads();

    int wf = tid >> 5, lane = tid & 31;
    float tv[5];
    {
        int row = nc * 8 + wf;
        #pragma unroll
        for (int k = 0; k < 5; k++) tv[k] = g_top5[row * 5 + k] * bsc + bsh;
    }
    if (lane < 25) {
        float a = s_up2b[lane];
        #pragma unroll
        for (int k = 0; k < 5; k++) a += tv[k] * s_up2w[lane * 5 + k];
        sh_t[wf][lane] = a;
    }
    __syncwarp();
    if (lane < 25) {
        float a = 0.f;
        #pragma unroll
        for (int i = 0; i < 25; i++) a += sh_t[wf][i] * s_wW[i * 25 + lane];
        sh_u[wf][lane] = tanhf(a);
    }
    __syncwarp();
    if (lane < 5) {
        float a = 0.f;
        #pragma unroll
        for (int i = 0; i < 25; i++) a += sh_u[wf][i] * s_wproj[i * 5 + lane];
        sh_l[wf][lane] = a;
    }
    __syncwarp();
    if (lane < 5) {
        float mx = sh_l[wf][0];
        #pragma unroll
        for (int j = 1; j < 5; j++) mx = fmaxf(mx, sh_l[wf][j]);
        float den = 0.f;
        #pragma unroll
        for (int j = 0; j < 5; j++) den += expf(sh_l[wf][j] - mx);
        float att = expf(sh_l[wf][lane] - mx) / den;
        float t3  = s_up3b[lane];
        #pragma unroll
        for (int i = 0; i < 25; i++) t3 += sh_t[wf][i] * s_up3w[lane * 25 + i];
        sh_m[wf][lane] = t3 * att;
    }
    __syncwarp();
    float c0 = 0.f, c1 = 0.f;
    if (lane < 25) {
        float sc = s_up2b[lane];
        #pragma unroll
        for (int k = 0; k < 5; k++) sc += sh_m[wf][k] * s_up2w[lane * 5 + k];
        c0 = sc * (float)(lane / 5);   // coords col 0 (ii)
        c1 = sc * (float)(lane % 5);   // coords col 1 (jj)
    }
    #pragma unroll
    for (int o = 16; o; o >>= 1) {
        c0 += __shfl_xor_sync(0xffffffffu, c0, o);
        c1 += __shfl_xor_sync(0xffffffffu, c1, o);
    }
    if (lane == 0) { sh_cen[wf][0] = c0; sh_cen[wf][1] = c1; }
    __syncthreads();

    // temporal attention (7 diffs, 20-dim embed)
    if (tid < 140) {
        int j = tid / 20, k = tid % 20;
        float d0 = sh_cen[j + 1][0] - sh_cen[j][0];
        float d1 = sh_cen[j + 1][1] - sh_cen[j][1];
        sh_d[j][k] = d0 * s_upw[k * 2] + d1 * s_upw[k * 2 + 1] + s_upb[k];
    }
    __syncthreads();
    if (tid < 140) {
        int i = tid / 20, k = tid % 20;
        float a = 0.f;
        #pragma unroll
        for (int j = 0; j < 7; j++) a += s_wW2[i * 7 + j] * sh_d[j][k];
        sh_u2[i][k] = tanhf(a);
    }
    __syncthreads();
    if (tid < 7) {
        float a = 0.f;
        #pragma unroll
        for (int k = 0; k < 20; k++) a += sh_u2[tid][k] * s_wproj2[k];
        sh_l2[tid] = a;
    }
    __syncthreads();
    if (tid < 7) {
        float mx = sh_l2[0];
        #pragma unroll
        for (int i = 1; i < 7; i++) mx = fmaxf(mx, sh_l2[i]);
        float den = 0.f;
        #pragma unroll
        for (int i = 0; i < 7; i++) den += expf(sh_l2[i] - mx);
        sh_a2[tid] = expf(sh_l2[tid] - mx) / den;
    }
    __syncthreads();
    if (tid < 140) {
        int i = tid / 20, k = tid % 20;
        g_si[(nc * 7 + i) * 20 + k] = sh_d[i][k] * sh_a2[i];
    }
}

// ---------------------------------------------------------------------------
// conv1: (N,64,7,20) -> (N,128,7,10), kernel (1,3), stride (1,2), pad W=1.
// Block = (n,i); 256 threads: o = tid&127, half = tid>>7 (j-halves).
// Weights read as one coalesced float4 per cc (packed, L2-resident).
// Input staged in shared with a left zero-pad (stride 21) -> uniform inner loop.
__global__ void k_conv1() {
    int b = blockIdx.x; int n = b / 7, i = b % 7;
    __shared__ float s_in[64 * 21];
    int tid = threadIdx.x;   // 256
    for (int idx = tid; idx < 64 * 21; idx += 256) {
        int cc = idx / 21, k = idx % 21;
        s_in[idx] = (k == 0) ? 0.f : g_si[((n * 64 + cc) * 7 + i) * 20 + (k - 1)];
    }
    __syncthreads();

    int o = tid & 127, half = tid >> 7;
    int jbase = half * 5;
    const float4* wp = reinterpret_cast<const float4*>(p1w) + o;
    float x[5] = {0.f, 0.f, 0.f, 0.f, 0.f};
    #pragma unroll 4
    for (int cc = 0; cc < 64; cc++) {
        float4 w = wp[cc * 128];
        const float* s = &s_in[cc * 21 + jbase * 2];
        #pragma unroll
        for (int q = 0; q < 5; q++)
            x[q] += s[2*q] * w.x + s[2*q+1] * w.y + s[2*q+2] * w.z;
    }
    float ps = 0.f, pq = 0.f;
    #pragma unroll
    for (int q = 0; q < 5; q++) {
        g_x1[((n * 128 + o) * 7 + i) * 10 + jbase + q] = x[q];
        ps += x[q]; pq += x[q] * x[q];
    }
    atomicAdd(&g_s1[o], ps);
    atomicAdd(&g_q1[o], pq);
}

// ---------------------------------------------------------------------------
// bn1 + tanh + conv2: (N,128,7,10) -> (N,256,7,5). Accumulates bn2 stats.
// Block = (n,i); 256 threads (one per o). Packed float4 weights (L2-resident).
__global__ void k_conv2(const float* __restrict__ g1, const float* __restrict__ b1) {
    int b = blockIdx.x; int n = b / 7, i = b % 7;
    __shared__ float s_a[128 * 11];
    __shared__ float s_sc[128], s_sh[128];
    int tid = threadIdx.x;   // 256
    if (tid < 128) {
        float mean = g_s1[tid] / 1120.f;
        float var  = g_q1[tid] / 1120.f - mean * mean;
        float sc   = rsqrtf(var + EPS) * g1[tid];
        s_sc[tid] = sc; s_sh[tid] = b1[tid] - mean * sc;
    }
    __syncthreads();
    for (int idx = tid; idx < 128 * 11; idx += 256) {
        int cc = idx / 11, k = idx % 11;
        float v = 0.f;
        if (k > 0) {
            float t = g_x1[((n * 128 + cc) * 7 + i) * 10 + (k - 1)];
            v = tanhf(t * s_sc[cc] + s_sh[cc]);
        }
        s_a[idx] = v;
    }
    __syncthreads();

    int o = tid;
    const float4* wp = reinterpret_cast<const float4*>(p2w) + o;
    float y[5] = {0.f, 0.f, 0.f, 0.f, 0.f};
    #pragma unroll 4
    for (int cc = 0; cc < 128; cc++) {
        float4 w = wp[cc * 256];
        const float* s = &s_a[cc * 11];
        #pragma unroll
        for (int q = 0; q < 5; q++)
            y[q] += s[2*q] * w.x + s[2*q+1] * w.y + s[2*q+2] * w.z;
    }
    float ps = 0.f, pq = 0.f;
    #pragma unroll
    for (int q = 0; q < 5; q++) {
        g_x2[((n * 256 + o) * 7 + i) * 5 + q] = y[q];
        ps += y[q]; pq += y[q] * y[q];
    }
    atomicAdd(&g_s2[o], ps);
    atomicAdd(&g_q2[o], pq);
}

// ---------------------------------------------------------------------------
// bn2 + tanh + mean over W(5) -> out (N,256,7,1)
__global__ void k_final(const float* __restrict__ g2, const float* __restrict__ b2,
                        float* __restrict__ out) {
    int b = blockIdx.x; int n = b / 7, i = b % 7;
    int o = threadIdx.x;   // 256
    float mean = g_s2[o] / 560.f;
    float var  = g_q2[o] / 560.f - mean * mean;
    float sc   = rsqrtf(var + EPS) * g2[o];
    float sh   = b2[o] - mean * sc;
    float acc = 0.f;
    #pragma unroll
    for (int j = 0; j < 5; j++)
        acc += tanhf(g_x2[((n * 256 + o) * 7 + i) * 5 + j] * sc + sh);
    out[(n * 256 + o) * 7 + i] = acc * 0.2f;
}

// ---------------------------------------------------------------------------
extern "C" void kernel_launch(void* const* d_in, const int* in_sizes, int n_in,
                              void* d_out, int out_size) {
    const float* h       = (const float*)d_in[0];
    const float* bn0_g   = (const float*)d_in[1];
    const float* bn0_b   = (const float*)d_in[2];
    const float* up_w    = (const float*)d_in[3];
    const float* up_b    = (const float*)d_in[4];
    const float* up2_w   = (const float*)d_in[5];
    const float* up2_b   = (const float*)d_in[6];
    const float* up3_w   = (const float*)d_in[7];
    const float* up3_b   = (const float*)d_in[8];
    const float* wW      = (const float*)d_in[9];
    const float* wproj   = (const float*)d_in[10];
    const float* wW2     = (const float*)d_in[11];
    const float* wproj2  = (const float*)d_in[12];
    const float* conv1_w = (const float*)d_in[13];
    const float* bn1_g   = (const float*)d_in[14];
    const float* bn1_b   = (const float*)d_in[15];
    const float* conv2_w = (const float*)d_in[16];
    const float* bn2_g   = (const float*)d_in[17];
    const float* bn2_b   = (const float*)d_in[18];

    k_prep <<<641, 256>>>(conv1_w, conv2_w);
    k_topk <<<ROWS, 256>>>(h);
    k_attn <<<Nn * Cc, 256>>>(bn0_g, bn0_b, up_w, up_b, up2_w, up2_b,
                              up3_w, up3_b, wW, wproj, wW2, wproj2);
    k_conv1<<<Nn * 7, 256>>>();
    k_conv2<<<Nn * 7, 256>>>(bn1_g, bn1_b);
    k_final<<<Nn * 7, 256>>>(bn2_g, bn2_b, (float*)d_out);
}